// round 4
// baseline (speedup 1.0000x reference)
#include <cuda_runtime.h>
#include <math.h>

// Problem constants
#define BB     2
#define HEADS  8
#define LEVELS 3
#define POINTS 4
#define CC     256
#define HD     32          // CC / HEADS
#define NV     5376        // 64*64 + 32*32 + 16*16
#define NQ     5376
#define TP     96          // HEADS*LEVELS*POINTS
#define TP2    192

// Scratch (static device allocations — allowed by harness rules)
__device__ float g_v[BB * NV * CC];        // value @ Wv^T + bv, layout (b, n, h, hd)
__device__ float g_off[BB * NQ * TP2];     // sampling offsets
__device__ float g_a[BB * NQ * TP];        // attention logits (raw; softmax fused into sampler)
__device__ float g_tmp[BB * NQ * CC];      // sampled output, layout (b, q, h, hd)

// ---------------------------------------------------------------------------
// GEMM: C[m,n] = sum_k A[m,k] * W[n,k] + bias[n]
// 64x64 tile, K-tile 16, 256 threads, 4x4 per-thread register block.
// ---------------------------------------------------------------------------
#define Bm 64
#define Bn 64
#define Bk 16

__global__ void __launch_bounds__(256) gemm_bias_kernel(
    const float* __restrict__ A, const float* __restrict__ W,
    const float* __restrict__ bias, float* __restrict__ C,
    int M, int N, int K)
{
    __shared__ float As[Bk][Bm];   // [16][64], stored transposed: As[k][m]
    __shared__ float Bs[Bk][Bn];   // [16][64], stored transposed: Bs[k][n]

    const int tid = threadIdx.x;
    const int tx = tid & 15;          // 0..15 -> n group
    const int ty = tid >> 4;          // 0..15 -> m group
    const int m0 = blockIdx.y * Bm;
    const int n0 = blockIdx.x * Bn;

    float acc[4][4] = {};

    for (int k0 = 0; k0 < K; k0 += Bk) {
        // load A tile (64 rows x 16 k) transposed into As[k][m]
#pragma unroll
        for (int i = 0; i < 4; i++) {
            int idx = tid + i * 256;
            int r = idx >> 4;         // 0..63 (m within tile)
            int c = idx & 15;         // 0..15 (k within tile)
            int gm = m0 + r;
            As[c][r] = (gm < M) ? A[(size_t)gm * K + k0 + c] : 0.f;
        }
        // load W tile (64 rows x 16 k) transposed into Bs[k][n]
#pragma unroll
        for (int i = 0; i < 4; i++) {
            int idx = tid + i * 256;
            int r = idx >> 4;
            int c = idx & 15;
            int gn = n0 + r;
            Bs[c][r] = (gn < N) ? W[(size_t)gn * K + k0 + c] : 0.f;
        }
        __syncthreads();

#pragma unroll
        for (int k = 0; k < Bk; k++) {
            float a[4], b[4];
#pragma unroll
            for (int i = 0; i < 4; i++) a[i] = As[k][ty * 4 + i];
#pragma unroll
            for (int j = 0; j < 4; j++) b[j] = Bs[k][tx * 4 + j];
#pragma unroll
            for (int i = 0; i < 4; i++)
#pragma unroll
                for (int j = 0; j < 4; j++)
                    acc[i][j] = fmaf(a[i], b[j], acc[i][j]);
        }
        __syncthreads();
    }

#pragma unroll
    for (int i = 0; i < 4; i++) {
        int gm = m0 + ty * 4 + i;
        if (gm >= M) continue;
#pragma unroll
        for (int j = 0; j < 4; j++) {
            int gn = n0 + tx * 4 + j;
            if (gn < N) C[(size_t)gm * N + gn] = acc[i][j] + bias[gn];
        }
    }
}

// ---------------------------------------------------------------------------
// Bilinear sampling with fused 12-wide softmax.
// One warp per (b, q, head); lane = channel (HD = 32).
// g_tmp[b, q, h, hd] = sum_{lvl,p} softmax(a)[lvl,p] * bilinear(v_level, loc)
// ---------------------------------------------------------------------------
__global__ void __launch_bounds__(256) sample_kernel(
    const float* __restrict__ refpts)
{
    const int warp = (blockIdx.x * blockDim.x + threadIdx.x) >> 5;
    const int lane = threadIdx.x & 31;
    const int total = BB * NQ * HEADS;
    if (warp >= total) return;

    const int h = warp % HEADS;
    const int bq = warp / HEADS;      // b*NQ + q
    const int b = bq / NQ;

    const float rx = refpts[(size_t)bq * 2 + 0];
    const float ry = refpts[(size_t)bq * 2 + 1];

    const float* off = g_off + (size_t)bq * TP2 + h * (LEVELS * POINTS * 2);
    const float* logit = g_a + (size_t)bq * TP + h * (LEVELS * POINTS);

    // Fused softmax over the 12 attention logits (redundant per lane; cheap).
    float e[LEVELS * POINTS];
    float mx = -INFINITY;
#pragma unroll
    for (int i = 0; i < LEVELS * POINTS; i++) {
        e[i] = logit[i];
        mx = fmaxf(mx, e[i]);
    }
    float s = 0.f;
#pragma unroll
    for (int i = 0; i < LEVELS * POINTS; i++) { e[i] = __expf(e[i] - mx); s += e[i]; }
    const float inv = 1.f / s;

    const int lvl_start[LEVELS] = {0, 4096, 5120};
    const int lvl_dim[LEVELS]   = {64, 32, 16};

    float acc = 0.f;

#pragma unroll
    for (int lvl = 0; lvl < LEVELS; lvl++) {
        const int Wd = lvl_dim[lvl];
        const int Hd = lvl_dim[lvl];
        const int base_n = b * NV + lvl_start[lvl];
#pragma unroll
        for (int p = 0; p < POINTS; p++) {
            float lx = rx + off[(lvl * POINTS + p) * 2 + 0];
            float ly = ry + off[(lvl * POINTS + p) * 2 + 1];
            lx = fminf(fmaxf(lx, 0.f), 1.f);
            ly = fminf(fmaxf(ly, 0.f), 1.f);
            const float aw = e[lvl * POINTS + p] * inv;

            const float x = lx * Wd - 0.5f;
            const float y = ly * Hd - 0.5f;
            const float x0f = floorf(x);
            const float y0f = floorf(y);
            const int x0 = (int)x0f;
            const int y0 = (int)y0f;
            const float wx1 = x - x0f;
            const float wy1 = y - y0f;
            const float wx0 = 1.f - wx1;
            const float wy0 = 1.f - wy1;

#pragma unroll
            for (int dy = 0; dy < 2; dy++) {
#pragma unroll
                for (int dx = 0; dx < 2; dx++) {
                    const int ix = x0 + dx;
                    const int iy = y0 + dy;
                    if (ix >= 0 && ix < Wd && iy >= 0 && iy < Hd) {
                        const float w = (dx ? wx1 : wx0) * (dy ? wy1 : wy0);
                        const size_t vi =
                            (((size_t)(base_n + iy * Wd + ix)) * HEADS + h) * HD + lane;
                        acc = fmaf(aw * w, g_v[vi], acc);
                    }
                }
            }
        }
    }

    g_tmp[((size_t)bq * HEADS + h) * HD + lane] = acc;
}

// ---------------------------------------------------------------------------
extern "C" void kernel_launch(void* const* d_in, const int* in_sizes, int n_in,
                              void* d_out, int out_size)
{
    const float* query  = (const float*)d_in[0];
    const float* refpts = (const float*)d_in[1];
    const float* value  = (const float*)d_in[2];
    const float* Wv     = (const float*)d_in[3];
    const float* bv     = (const float*)d_in[4];
    const float* Woff   = (const float*)d_in[5];
    const float* boff   = (const float*)d_in[6];
    const float* Wa     = (const float*)d_in[7];
    const float* ba     = (const float*)d_in[8];
    const float* Wo     = (const float*)d_in[9];
    const float* bo     = (const float*)d_in[10];
    float* out = (float*)d_out;

    float *p_v, *p_off, *p_a, *p_tmp;
    cudaGetSymbolAddress((void**)&p_v,   g_v);
    cudaGetSymbolAddress((void**)&p_off, g_off);
    cudaGetSymbolAddress((void**)&p_a,   g_a);
    cudaGetSymbolAddress((void**)&p_tmp, g_tmp);

    const int M = BB * NQ;             // 10752 (== BB*NV)
    const int gy = (M + Bm - 1) / Bm;  // 168

    // v = value @ Wv^T + bv
    gemm_bias_kernel<<<dim3(CC / Bn, gy), 256>>>(value, Wv, bv, p_v, M, CC, CC);
    // off = query @ Woff^T + boff
    gemm_bias_kernel<<<dim3(TP2 / Bn, gy), 256>>>(query, Woff, boff, p_off, M, TP2, CC);
    // a = query @ Wa^T + ba
    gemm_bias_kernel<<<dim3((TP + Bn - 1) / Bn, gy), 256>>>(query, Wa, ba, p_a, M, TP, CC);
    // bilinear sampling (softmax fused)
    sample_kernel<<<(BB * NQ * HEADS) / 8, 256>>>(refpts);
    // out = tmp @ Wo^T + bo
    gemm_bias_kernel<<<dim3(CC / Bn, gy), 256>>>(p_tmp, Wo, bo, out, M, CC, CC);
}

// round 5
// speedup vs baseline: 1.0247x; 1.0247x over previous
#include <cuda_runtime.h>
#include <math.h>

// Problem constants
#define BB     2
#define HEADS  8
#define LEVELS 3
#define POINTS 4
#define CC     256
#define HD     32          // CC / HEADS
#define NV     5376        // 64*64 + 32*32 + 16*16
#define NQ     5376
#define TP     96          // HEADS*LEVELS*POINTS
#define TP2    192

// Scratch (static device allocations — allowed by harness rules)
__device__ float g_v[BB * NV * CC];        // value @ Wv^T + bv, layout (b, n, h, hd)
__device__ float g_off[BB * NQ * TP2];     // sampling offsets
__device__ float g_a[BB * NQ * TP];        // attention logits (softmax fused in sampler)
__device__ float g_tmp[BB * NQ * CC];      // sampled output, layout (b, q, h, hd)

// ---------------------------------------------------------------------------
// GEMM: C[m,n] = sum_k A[m,k] * W[n,k] + bias[n]
// 128x64 tile, K-tile 16, 256 threads, 8x4 per-thread register block,
// float4-vectorized global and shared loads.
// Requirements: M % 128 == 0, K % 16 == 0 (true here: M=10752, K=256).
// N guarded (N in {96, 192, 256}).
// ---------------------------------------------------------------------------
#define GBm 128
#define GBn 64
#define GBk 16

__global__ void __launch_bounds__(256) gemm_bias_kernel(
    const float* __restrict__ A, const float* __restrict__ W,
    const float* __restrict__ bias, float* __restrict__ C,
    int M, int N, int K)
{
    __shared__ float As[GBk][GBm];   // [16][128] transposed: As[k][m]
    __shared__ float Bs[GBk][GBn];   // [16][64]  transposed: Bs[k][n]

    const int tid = threadIdx.x;
    const int tx = tid & 15;          // n group: 4 columns each
    const int ty = tid >> 4;          // m group: 8 rows each
    const int m0 = blockIdx.y * GBm;
    const int n0 = blockIdx.x * GBn;

    float acc[8][4] = {};

    // B-tile load mapping: 1 float4 per thread
    const int br = tid >> 2;          // 0..63  (n within tile)
    const int bc = tid & 3;           // float4 index along k

    for (int k0 = 0; k0 < K; k0 += GBk) {
        // A tile: 128 x 16 = 512 float4s, 2 per thread, stored transposed
#pragma unroll
        for (int j = 0; j < 2; j++) {
            int i = tid * 2 + j;
            int r = i >> 2;           // 0..127 (m within tile)
            int c = i & 3;            // float4 index along k
            float4 va = *(const float4*)&A[(size_t)(m0 + r) * K + k0 + c * 4];
            As[c * 4 + 0][r] = va.x;
            As[c * 4 + 1][r] = va.y;
            As[c * 4 + 2][r] = va.z;
            As[c * 4 + 3][r] = va.w;
        }
        // W tile: 64 x 16 = 256 float4s, 1 per thread, stored transposed
        {
            int gn = n0 + br;
            float4 vb = make_float4(0.f, 0.f, 0.f, 0.f);
            if (gn < N) vb = *(const float4*)&W[(size_t)gn * K + k0 + bc * 4];
            Bs[bc * 4 + 0][br] = vb.x;
            Bs[bc * 4 + 1][br] = vb.y;
            Bs[bc * 4 + 2][br] = vb.z;
            Bs[bc * 4 + 3][br] = vb.w;
        }
        __syncthreads();

#pragma unroll
        for (int k = 0; k < GBk; k++) {
            float a[8], b[4];
            *(float4*)&a[0] = *(const float4*)&As[k][ty * 8];
            *(float4*)&a[4] = *(const float4*)&As[k][ty * 8 + 4];
            *(float4*)&b[0] = *(const float4*)&Bs[k][tx * 4];
#pragma unroll
            for (int i = 0; i < 8; i++)
#pragma unroll
                for (int j = 0; j < 4; j++)
                    acc[i][j] = fmaf(a[i], b[j], acc[i][j]);
        }
        __syncthreads();
    }

    // Epilogue: vectorized float4 stores (N % 4 == 0 always; guard whole float4)
    const int gn = n0 + tx * 4;
    if (gn < N) {
        const float4 bv4 = *(const float4*)&bias[gn];
#pragma unroll
        for (int i = 0; i < 8; i++) {
            int gm = m0 + ty * 8 + i;
            float4 o;
            o.x = acc[i][0] + bv4.x;
            o.y = acc[i][1] + bv4.y;
            o.z = acc[i][2] + bv4.z;
            o.w = acc[i][3] + bv4.w;
            *(float4*)&C[(size_t)gm * N + gn] = o;
        }
    }
}

// ---------------------------------------------------------------------------
// Bilinear sampling with fused 12-wide softmax. 32-bit index arithmetic.
// One warp per (b, q, head); lane = channel (HD = 32).
// ---------------------------------------------------------------------------
__global__ void __launch_bounds__(256) sample_kernel(
    const float* __restrict__ refpts)
{
    const int warp = (blockIdx.x * blockDim.x + threadIdx.x) >> 5;
    const int lane = threadIdx.x & 31;
    if (warp >= BB * NQ * HEADS) return;

    const int h = warp % HEADS;
    const int bq = warp / HEADS;      // b*NQ + q
    const int b = bq / NQ;

    const float rx = refpts[bq * 2 + 0];
    const float ry = refpts[bq * 2 + 1];

    const float* __restrict__ off = g_off + bq * TP2 + h * (LEVELS * POINTS * 2);
    const float* __restrict__ logit = g_a + bq * TP + h * (LEVELS * POINTS);

    // Fused softmax over the 12 attention logits (redundant per lane; cheap).
    float e[LEVELS * POINTS];
    float mx = -INFINITY;
#pragma unroll
    for (int i = 0; i < LEVELS * POINTS; i++) {
        e[i] = logit[i];
        mx = fmaxf(mx, e[i]);
    }
    float s = 0.f;
#pragma unroll
    for (int i = 0; i < LEVELS * POINTS; i++) { e[i] = __expf(e[i] - mx); s += e[i]; }
    const float inv = 1.f / s;

    const int lvl_start[LEVELS] = {0, 4096, 5120};
    const int lvl_dim[LEVELS]   = {64, 32, 16};

    const int chan = h * HD + lane;   // channel within the 256-wide row
    float acc = 0.f;

#pragma unroll
    for (int lvl = 0; lvl < LEVELS; lvl++) {
        const int Wd = lvl_dim[lvl];
        const int Hd = lvl_dim[lvl];
        // 32-bit base offset of this level's (0,0) row for this channel
        const int base = (b * NV + lvl_start[lvl]) * CC + chan;
        const float fW = (float)Wd;
        const float fH = (float)Hd;
#pragma unroll
        for (int p = 0; p < POINTS; p++) {
            float lx = rx + off[(lvl * POINTS + p) * 2 + 0];
            float ly = ry + off[(lvl * POINTS + p) * 2 + 1];
            lx = fminf(fmaxf(lx, 0.f), 1.f);
            ly = fminf(fmaxf(ly, 0.f), 1.f);
            const float aw = e[lvl * POINTS + p] * inv;

            const float x = fmaf(lx, fW, -0.5f);
            const float y = fmaf(ly, fH, -0.5f);
            const float x0f = floorf(x);
            const float y0f = floorf(y);
            const int x0 = (int)x0f;
            const int y0 = (int)y0f;
            const float wx1 = x - x0f;
            const float wy1 = y - y0f;
            const float wx0 = 1.f - wx1;
            const float wy0 = 1.f - wy1;

            // Corner weights scaled by attention weight
            const float w00 = aw * wx0 * wy0;
            const float w01 = aw * wx1 * wy0;
            const float w10 = aw * wx0 * wy1;
            const float w11 = aw * wx1 * wy1;

            const bool xin0 = (x0 >= 0);
            const bool xin1 = (x0 + 1 < Wd);
            const bool yin0 = (y0 >= 0);
            const bool yin1 = (y0 + 1 < Hd);

            const int row0 = base + (y0 * Wd + x0) * CC;       // (y0, x0)
            if (yin0) {
                if (xin0) acc = fmaf(w00, g_v[row0], acc);
                if (xin1) acc = fmaf(w01, g_v[row0 + CC], acc);
            }
            if (yin1) {
                const int row1 = row0 + Wd * CC;
                if (xin0) acc = fmaf(w10, g_v[row1], acc);
                if (xin1) acc = fmaf(w11, g_v[row1 + CC], acc);
            }
        }
    }

    g_tmp[(bq * HEADS + h) * HD + lane] = acc;
}

// ---------------------------------------------------------------------------
extern "C" void kernel_launch(void* const* d_in, const int* in_sizes, int n_in,
                              void* d_out, int out_size)
{
    const float* query  = (const float*)d_in[0];
    const float* refpts = (const float*)d_in[1];
    const float* value  = (const float*)d_in[2];
    const float* Wv     = (const float*)d_in[3];
    const float* bv     = (const float*)d_in[4];
    const float* Woff   = (const float*)d_in[5];
    const float* boff   = (const float*)d_in[6];
    const float* Wa     = (const float*)d_in[7];
    const float* ba     = (const float*)d_in[8];
    const float* Wo     = (const float*)d_in[9];
    const float* bo     = (const float*)d_in[10];
    float* out = (float*)d_out;

    float *p_v, *p_off, *p_a, *p_tmp;
    cudaGetSymbolAddress((void**)&p_v,   g_v);
    cudaGetSymbolAddress((void**)&p_off, g_off);
    cudaGetSymbolAddress((void**)&p_a,   g_a);
    cudaGetSymbolAddress((void**)&p_tmp, g_tmp);

    const int M = BB * NQ;              // 10752 = 84 * 128
    const int gy = M / GBm;             // 84

    // v = value @ Wv^T + bv
    gemm_bias_kernel<<<dim3(CC / GBn, gy), 256>>>(value, Wv, bv, p_v, M, CC, CC);
    // off = query @ Woff^T + boff
    gemm_bias_kernel<<<dim3(TP2 / GBn, gy), 256>>>(query, Woff, boff, p_off, M, TP2, CC);
    // a = query @ Wa^T + ba
    gemm_bias_kernel<<<dim3((TP + GBn - 1) / GBn, gy), 256>>>(query, Wa, ba, p_a, M, TP, CC);
    // bilinear sampling (softmax fused)
    sample_kernel<<<(BB * NQ * HEADS) / 8, 256>>>(refpts);
    // out = tmp @ Wo^T + bo
    gemm_bias_kernel<<<dim3(CC / GBn, gy), 256>>>(p_tmp, Wo, bo, out, M, CC, CC);
}

// round 7
// speedup vs baseline: 2.6978x; 2.6328x over previous
#include <cuda_runtime.h>
#include <math.h>

// Problem constants
#define BB     2
#define HEADS  8
#define LEVELS 3
#define POINTS 4
#define CC     256
#define HD     32          // CC / HEADS
#define NV     5376        // 64*64 + 32*32 + 16*16
#define NQ     5376
#define TP     96          // HEADS*LEVELS*POINTS
#define TP2    192

// Scratch (static device allocations — allowed by harness rules)
__device__ float g_v[BB * NV * CC];        // value @ Wv^T + bv, layout (b, n, h, hd)
__device__ float g_off[BB * NQ * TP2];     // sampling offsets
__device__ float g_a[BB * NQ * TP];        // attention logits (softmax fused in sampler)
__device__ float g_tmp[BB * NQ * CC];      // sampled output, layout (b, q, h, hd)

// ---------------------------------------------------------------------------
// Tensor-core GEMM (tf32 mma.sync): C[m,n] = sum_k A[m,k]*W[n,k] + bias[n]
// Block tile 128m x 64n, k-tile 32. 256 threads = 8 warps, each warp 32m x 32n
// (2 m16 tiles x 4 n8 tiles of m16n8k8). fp32 accum; inputs rounded to tf32.
// Requires M % 128 == 0, K % 32 == 0 (M=10752, K=256). N guarded (96/192/256).
// ---------------------------------------------------------------------------
#define GBm 128
#define GBn 64
#define GBk 32
#define SSTR 36   // smem row stride in words (32 + 4 pad -> conflict-free)

__device__ __forceinline__ unsigned f2tf32(float f) {
    unsigned u;
    asm("cvt.rna.tf32.f32 %0, %1;" : "=r"(u) : "f"(f));
    return u;
}

__global__ void __launch_bounds__(256) gemm_tf32_kernel(
    const float* __restrict__ A, const float* __restrict__ W,
    const float* __restrict__ bias, float* __restrict__ C,
    int M, int N, int K)
{
    __shared__ unsigned As[GBm][SSTR];   // A tile, [m][k], tf32 bits
    __shared__ unsigned Ws[GBn][SSTR];   // W tile, [n][k], tf32 bits

    const int tid  = threadIdx.x;
    const int lane = tid & 31;
    const int warp = tid >> 5;
    const int wm   = warp >> 1;          // 0..3 -> m offset wm*32
    const int wn   = warp & 1;           // 0..1 -> n offset wn*32
    const int m0   = blockIdx.y * GBm;
    const int n0   = blockIdx.x * GBn;

    const int grp = lane >> 2;           // groupID (0..7)
    const int tig = lane & 3;            // threadID in group (0..3)

    float c[2][4][4];
#pragma unroll
    for (int mt = 0; mt < 2; mt++)
#pragma unroll
        for (int nt = 0; nt < 4; nt++)
#pragma unroll
            for (int i = 0; i < 4; i++) c[mt][nt][i] = 0.f;

    for (int k0 = 0; k0 < K; k0 += GBk) {
        // ---- fill A tile: 128 rows x 32 k = 1024 float4, 4 per thread ----
#pragma unroll
        for (int j = 0; j < 4; j++) {
            int idx = tid + j * 256;
            int r = idx >> 3;            // 0..127
            int cc4 = idx & 7;           // float4 index along k
            float4 f = *(const float4*)&A[(size_t)(m0 + r) * K + k0 + cc4 * 4];
            uint4 u;
            u.x = f2tf32(f.x); u.y = f2tf32(f.y);
            u.z = f2tf32(f.z); u.w = f2tf32(f.w);
            *(uint4*)&As[r][cc4 * 4] = u;
        }
        // ---- fill W tile: 64 rows x 32 k = 512 float4, 2 per thread ----
#pragma unroll
        for (int j = 0; j < 2; j++) {
            int idx = tid + j * 256;
            int r = idx >> 3;            // 0..63
            int cc4 = idx & 7;
            int gn = n0 + r;
            float4 f = make_float4(0.f, 0.f, 0.f, 0.f);
            if (gn < N) f = *(const float4*)&W[(size_t)gn * K + k0 + cc4 * 4];
            uint4 u;
            u.x = f2tf32(f.x); u.y = f2tf32(f.y);
            u.z = f2tf32(f.z); u.w = f2tf32(f.w);
            *(uint4*)&Ws[r][cc4 * 4] = u;
        }
        __syncthreads();

#pragma unroll
        for (int kk = 0; kk < GBk; kk += 8) {
            // A fragments: 2 m-tiles x 4 regs
            unsigned a[2][4];
#pragma unroll
            for (int mt = 0; mt < 2; mt++) {
                int rb = wm * 32 + mt * 16;
                a[mt][0] = As[rb + grp][kk + tig];
                a[mt][1] = As[rb + grp + 8][kk + tig];
                a[mt][2] = As[rb + grp][kk + tig + 4];
                a[mt][3] = As[rb + grp + 8][kk + tig + 4];
            }
            // B fragments: 4 n-tiles x 2 regs (B[k][n] = W[n][k])
            unsigned b[4][2];
#pragma unroll
            for (int nt = 0; nt < 4; nt++) {
                int cb = wn * 32 + nt * 8;
                b[nt][0] = Ws[cb + grp][kk + tig];
                b[nt][1] = Ws[cb + grp][kk + tig + 4];
            }
#pragma unroll
            for (int mt = 0; mt < 2; mt++)
#pragma unroll
                for (int nt = 0; nt < 4; nt++) {
                    asm volatile(
                        "mma.sync.aligned.m16n8k8.row.col.f32.tf32.tf32.f32 "
                        "{%0,%1,%2,%3}, {%4,%5,%6,%7}, {%8,%9}, {%0,%1,%2,%3};"
                        : "+f"(c[mt][nt][0]), "+f"(c[mt][nt][1]),
                          "+f"(c[mt][nt][2]), "+f"(c[mt][nt][3])
                        : "r"(a[mt][0]), "r"(a[mt][1]), "r"(a[mt][2]), "r"(a[mt][3]),
                          "r"(b[nt][0]), "r"(b[nt][1]));
                }
        }
        __syncthreads();
    }

    // ---- epilogue: C rows m0+wm*32+mt*16+{grp, grp+8}, cols n0+wn*32+nt*8+2*tig ----
#pragma unroll
    for (int nt = 0; nt < 4; nt++) {
        int gn = n0 + wn * 32 + nt * 8 + tig * 2;
        if (gn >= N) continue;
        float b0 = bias[gn];
        float b1 = bias[gn + 1];
#pragma unroll
        for (int mt = 0; mt < 2; mt++) {
            int gm = m0 + wm * 32 + mt * 16 + grp;
            float2 o0 = make_float2(c[mt][nt][0] + b0, c[mt][nt][1] + b1);
            float2 o1 = make_float2(c[mt][nt][2] + b0, c[mt][nt][3] + b1);
            *(float2*)&C[(size_t)gm * N + gn] = o0;
            *(float2*)&C[(size_t)(gm + 8) * N + gn] = o1;
        }
    }
}

// ---------------------------------------------------------------------------
// Bilinear sampling with fused 12-wide softmax (R4 version — measured 82.9us).
// One warp per (b, q, head); lane = channel (HD = 32).
// ---------------------------------------------------------------------------
__global__ void __launch_bounds__(256) sample_kernel(
    const float* __restrict__ refpts)
{
    const int warp = (blockIdx.x * blockDim.x + threadIdx.x) >> 5;
    const int lane = threadIdx.x & 31;
    const int total = BB * NQ * HEADS;
    if (warp >= total) return;

    const int h = warp % HEADS;
    const int bq = warp / HEADS;      // b*NQ + q
    const int b = bq / NQ;

    const float rx = refpts[(size_t)bq * 2 + 0];
    const float ry = refpts[(size_t)bq * 2 + 1];

    const float* off = g_off + (size_t)bq * TP2 + h * (LEVELS * POINTS * 2);
    const float* logit = g_a + (size_t)bq * TP + h * (LEVELS * POINTS);

    // Fused softmax over the 12 attention logits (redundant per lane; cheap).
    float e[LEVELS * POINTS];
    float mx = -INFINITY;
#pragma unroll
    for (int i = 0; i < LEVELS * POINTS; i++) {
        e[i] = logit[i];
        mx = fmaxf(mx, e[i]);
    }
    float s = 0.f;
#pragma unroll
    for (int i = 0; i < LEVELS * POINTS; i++) { e[i] = __expf(e[i] - mx); s += e[i]; }
    const float inv = 1.f / s;

    const int lvl_start[LEVELS] = {0, 4096, 5120};
    const int lvl_dim[LEVELS]   = {64, 32, 16};

    float acc = 0.f;

#pragma unroll
    for (int lvl = 0; lvl < LEVELS; lvl++) {
        const int Wd = lvl_dim[lvl];
        const int Hd = lvl_dim[lvl];
        const int base_n = b * NV + lvl_start[lvl];
#pragma unroll
        for (int p = 0; p < POINTS; p++) {
            float lx = rx + off[(lvl * POINTS + p) * 2 + 0];
            float ly = ry + off[(lvl * POINTS + p) * 2 + 1];
            lx = fminf(fmaxf(lx, 0.f), 1.f);
            ly = fminf(fmaxf(ly, 0.f), 1.f);
            const float aw = e[lvl * POINTS + p] * inv;

            const float x = lx * Wd - 0.5f;
            const float y = ly * Hd - 0.5f;
            const float x0f = floorf(x);
            const float y0f = floorf(y);
            const int x0 = (int)x0f;
            const int y0 = (int)y0f;
            const float wx1 = x - x0f;
            const float wy1 = y - y0f;
            const float wx0 = 1.f - wx1;
            const float wy0 = 1.f - wy1;

#pragma unroll
            for (int dy = 0; dy < 2; dy++) {
#pragma unroll
                for (int dx = 0; dx < 2; dx++) {
                    const int ix = x0 + dx;
                    const int iy = y0 + dy;
                    if (ix >= 0 && ix < Wd && iy >= 0 && iy < Hd) {
                        const float w = (dx ? wx1 : wx0) * (dy ? wy1 : wy0);
                        const size_t vi =
                            (((size_t)(base_n + iy * Wd + ix)) * HEADS + h) * HD + lane;
                        acc = fmaf(aw * w, g_v[vi], acc);
                    }
                }
            }
        }
    }

    g_tmp[((size_t)bq * HEADS + h) * HD + lane] = acc;
}

// ---------------------------------------------------------------------------
extern "C" void kernel_launch(void* const* d_in, const int* in_sizes, int n_in,
                              void* d_out, int out_size)
{
    const float* query  = (const float*)d_in[0];
    const float* refpts = (const float*)d_in[1];
    const float* value  = (const float*)d_in[2];
    const float* Wv     = (const float*)d_in[3];
    const float* bv     = (const float*)d_in[4];
    const float* Woff   = (const float*)d_in[5];
    const float* boff   = (const float*)d_in[6];
    const float* Wa     = (const float*)d_in[7];
    const float* ba     = (const float*)d_in[8];
    const float* Wo     = (const float*)d_in[9];
    const float* bo     = (const float*)d_in[10];
    float* out = (float*)d_out;

    float *p_v, *p_off, *p_a, *p_tmp;
    cudaGetSymbolAddress((void**)&p_v,   g_v);
    cudaGetSymbolAddress((void**)&p_off, g_off);
    cudaGetSymbolAddress((void**)&p_a,   g_a);
    cudaGetSymbolAddress((void**)&p_tmp, g_tmp);

    const int M = BB * NQ;              // 10752 = 84 * 128
    const int gy = M / GBm;             // 84

    // v = value @ Wv^T + bv
    gemm_tf32_kernel<<<dim3(CC / GBn, gy), 256>>>(value, Wv, bv, p_v, M, CC, CC);
    // off = query @ Woff^T + boff
    gemm_tf32_kernel<<<dim3(TP2 / GBn, gy), 256>>>(query, Woff, boff, p_off, M, TP2, CC);
    // a = query @ Wa^T + ba
    gemm_tf32_kernel<<<dim3((TP + GBn - 1) / GBn, gy), 256>>>(query, Wa, ba, p_a, M, TP, CC);
    // bilinear sampling (softmax fused)
    sample_kernel<<<(BB * NQ * HEADS) / 8, 256>>>(refpts);
    // out = tmp @ Wo^T + bo
    gemm_tf32_kernel<<<dim3(CC / GBn, gy), 256>>>(p_tmp, Wo, bo, out, M, CC, CC);
}

// round 8
// speedup vs baseline: 3.0619x; 1.1350x over previous
#include <cuda_runtime.h>
#include <math.h>

// Problem constants
#define BB     2
#define HEADS  8
#define LEVELS 3
#define POINTS 4
#define CC     256
#define HD     32          // CC / HEADS
#define NV     5376        // 64*64 + 32*32 + 16*16
#define NQ     5376
#define TP     96          // HEADS*LEVELS*POINTS
#define TP2    192

// Scratch (static device allocations — allowed by harness rules)
__device__ float g_v[BB * NV * CC];        // value @ Wv^T + bv, layout (b, n, h, hd)
__device__ float g_off[BB * NQ * TP2];     // sampling offsets
__device__ float g_a[BB * NQ * TP];        // attention logits (softmax fused in sampler)
__device__ float g_tmp[BB * NQ * CC];      // sampled output, layout (b, q, h, hd)

// ---------------------------------------------------------------------------
// Tensor-core GEMM (tf32 mma.sync): C[m,n] = sum_k A[m,k]*W[n,k] + bias[n]
// Block tile 128m x 64n, k-tile 32. 256 threads = 8 warps, each warp 32m x 32n
// (2 m16 tiles x 4 n8 tiles of m16n8k8). fp32 accum; inputs rounded to tf32.
// (unchanged from R7 — measured ~67us aggregate for the 4 GEMMs)
// ---------------------------------------------------------------------------
#define GBm 128
#define GBn 64
#define GBk 32
#define SSTR 36   // smem row stride in words (32 + 4 pad -> conflict-free)

__device__ __forceinline__ unsigned f2tf32(float f) {
    unsigned u;
    asm("cvt.rna.tf32.f32 %0, %1;" : "=r"(u) : "f"(f));
    return u;
}

__global__ void __launch_bounds__(256) gemm_tf32_kernel(
    const float* __restrict__ A, const float* __restrict__ W,
    const float* __restrict__ bias, float* __restrict__ C,
    int M, int N, int K)
{
    __shared__ unsigned As[GBm][SSTR];   // A tile, [m][k], tf32 bits
    __shared__ unsigned Ws[GBn][SSTR];   // W tile, [n][k], tf32 bits

    const int tid  = threadIdx.x;
    const int lane = tid & 31;
    const int warp = tid >> 5;
    const int wm   = warp >> 1;          // 0..3 -> m offset wm*32
    const int wn   = warp & 1;           // 0..1 -> n offset wn*32
    const int m0   = blockIdx.y * GBm;
    const int n0   = blockIdx.x * GBn;

    const int grp = lane >> 2;           // groupID (0..7)
    const int tig = lane & 3;            // threadID in group (0..3)

    float c[2][4][4];
#pragma unroll
    for (int mt = 0; mt < 2; mt++)
#pragma unroll
        for (int nt = 0; nt < 4; nt++)
#pragma unroll
            for (int i = 0; i < 4; i++) c[mt][nt][i] = 0.f;

    for (int k0 = 0; k0 < K; k0 += GBk) {
        // ---- fill A tile: 128 rows x 32 k = 1024 float4, 4 per thread ----
#pragma unroll
        for (int j = 0; j < 4; j++) {
            int idx = tid + j * 256;
            int r = idx >> 3;            // 0..127
            int cc4 = idx & 7;           // float4 index along k
            float4 f = *(const float4*)&A[(size_t)(m0 + r) * K + k0 + cc4 * 4];
            uint4 u;
            u.x = f2tf32(f.x); u.y = f2tf32(f.y);
            u.z = f2tf32(f.z); u.w = f2tf32(f.w);
            *(uint4*)&As[r][cc4 * 4] = u;
        }
        // ---- fill W tile: 64 rows x 32 k = 512 float4, 2 per thread ----
#pragma unroll
        for (int j = 0; j < 2; j++) {
            int idx = tid + j * 256;
            int r = idx >> 3;            // 0..63
            int cc4 = idx & 7;
            int gn = n0 + r;
            float4 f = make_float4(0.f, 0.f, 0.f, 0.f);
            if (gn < N) f = *(const float4*)&W[(size_t)gn * K + k0 + cc4 * 4];
            uint4 u;
            u.x = f2tf32(f.x); u.y = f2tf32(f.y);
            u.z = f2tf32(f.z); u.w = f2tf32(f.w);
            *(uint4*)&Ws[r][cc4 * 4] = u;
        }
        __syncthreads();

#pragma unroll
        for (int kk = 0; kk < GBk; kk += 8) {
            // A fragments: 2 m-tiles x 4 regs
            unsigned a[2][4];
#pragma unroll
            for (int mt = 0; mt < 2; mt++) {
                int rb = wm * 32 + mt * 16;
                a[mt][0] = As[rb + grp][kk + tig];
                a[mt][1] = As[rb + grp + 8][kk + tig];
                a[mt][2] = As[rb + grp][kk + tig + 4];
                a[mt][3] = As[rb + grp + 8][kk + tig + 4];
            }
            // B fragments: 4 n-tiles x 2 regs (B[k][n] = W[n][k])
            unsigned b[4][2];
#pragma unroll
            for (int nt = 0; nt < 4; nt++) {
                int cb = wn * 32 + nt * 8;
                b[nt][0] = Ws[cb + grp][kk + tig];
                b[nt][1] = Ws[cb + grp][kk + tig + 4];
            }
#pragma unroll
            for (int mt = 0; mt < 2; mt++)
#pragma unroll
                for (int nt = 0; nt < 4; nt++) {
                    asm volatile(
                        "mma.sync.aligned.m16n8k8.row.col.f32.tf32.tf32.f32 "
                        "{%0,%1,%2,%3}, {%4,%5,%6,%7}, {%8,%9}, {%0,%1,%2,%3};"
                        : "+f"(c[mt][nt][0]), "+f"(c[mt][nt][1]),
                          "+f"(c[mt][nt][2]), "+f"(c[mt][nt][3])
                        : "r"(a[mt][0]), "r"(a[mt][1]), "r"(a[mt][2]), "r"(a[mt][3]),
                          "r"(b[nt][0]), "r"(b[nt][1]));
                }
        }
        __syncthreads();
    }

    // ---- epilogue ----
#pragma unroll
    for (int nt = 0; nt < 4; nt++) {
        int gn = n0 + wn * 32 + nt * 8 + tig * 2;
        if (gn >= N) continue;
        float b0 = bias[gn];
        float b1 = bias[gn + 1];
#pragma unroll
        for (int mt = 0; mt < 2; mt++) {
            int gm = m0 + wm * 32 + mt * 16 + grp;
            float2 o0 = make_float2(c[mt][nt][0] + b0, c[mt][nt][1] + b1);
            float2 o1 = make_float2(c[mt][nt][2] + b0, c[mt][nt][3] + b1);
            *(float2*)&C[(size_t)gm * N + gn] = o0;
            *(float2*)&C[(size_t)(gm + 8) * N + gn] = o1;
        }
    }
}

// ---------------------------------------------------------------------------
// Bilinear sampling with fused 12-wide softmax — corner-parallel float4 form.
// One warp per (b, q, head).
//   lane = cg*8 + ch4, cg = corner (dy = cg>>1, dx = cg&1), ch4 = float4 chunk.
// Each 8-lane group loads its corner's 128B head-row via one warp-wide LDG.128.
// Invalid corners: index clamped, weight zeroed (== reference clip+valid mask).
// Final cross-corner reduction via shfl_xor(8,16); lanes 0..7 store float4.
// ---------------------------------------------------------------------------
__global__ void __launch_bounds__(256) sample_kernel(
    const float* __restrict__ refpts)
{
    const int warp = (blockIdx.x * blockDim.x + threadIdx.x) >> 5;
    const int lane = threadIdx.x & 31;
    const int total = BB * NQ * HEADS;
    if (warp >= total) return;

    const int h  = warp % HEADS;
    const int bq = warp / HEADS;      // b*NQ + q
    const int b  = bq / NQ;

    const int cg  = lane >> 3;        // corner 0..3
    const int dx  = cg & 1;
    const int dy  = cg >> 1;
    const int ch4 = lane & 7;         // float4 chunk within head (channels ch4*4..+3)

    const float rx = refpts[bq * 2 + 0];
    const float ry = refpts[bq * 2 + 1];

    const float* __restrict__ off   = g_off + bq * TP2 + h * (LEVELS * POINTS * 2);
    const float* __restrict__ logit = g_a   + bq * TP  + h * (LEVELS * POINTS);

    // Fused softmax over the 12 attention logits (redundant per lane; cheap).
    float e[LEVELS * POINTS];
    float mx = -INFINITY;
#pragma unroll
    for (int i = 0; i < LEVELS * POINTS; i++) {
        e[i] = logit[i];
        mx = fmaxf(mx, e[i]);
    }
    float s = 0.f;
#pragma unroll
    for (int i = 0; i < LEVELS * POINTS; i++) { e[i] = __expf(e[i] - mx); s += e[i]; }
    const float inv = 1.f / s;

    const int lvl_start[LEVELS] = {0, 4096, 5120};
    const int lvl_dim[LEVELS]   = {64, 32, 16};

    float4 acc = make_float4(0.f, 0.f, 0.f, 0.f);

#pragma unroll
    for (int lvl = 0; lvl < LEVELS; lvl++) {
        const int Wd = lvl_dim[lvl];
        const int Hd = lvl_dim[lvl];
        // base index (fp32 floats) of this level, this head, this chunk
        const int base = (b * NV + lvl_start[lvl]) * CC + h * HD + ch4 * 4;
        const float fW = (float)Wd;
        const float fH = (float)Hd;
#pragma unroll
        for (int p = 0; p < POINTS; p++) {
            float lx = rx + off[(lvl * POINTS + p) * 2 + 0];
            float ly = ry + off[(lvl * POINTS + p) * 2 + 1];
            lx = fminf(fmaxf(lx, 0.f), 1.f);
            ly = fminf(fmaxf(ly, 0.f), 1.f);
            const float aw = e[lvl * POINTS + p] * inv;

            const float x = lx * fW - 0.5f;
            const float y = ly * fH - 0.5f;
            const float x0f = floorf(x);
            const float y0f = floorf(y);
            const int x0 = (int)x0f;
            const int y0 = (int)y0f;
            const float wx1 = x - x0f;
            const float wy1 = y - y0f;

            // this lane-group's corner
            const int ix = x0 + dx;
            const int iy = y0 + dy;
            float w = aw * (dx ? wx1 : 1.f - wx1) * (dy ? wy1 : 1.f - wy1);
            const bool valid = (ix >= 0) & (ix < Wd) & (iy >= 0) & (iy < Hd);
            w = valid ? w : 0.f;

            const int ixc = min(max(ix, 0), Wd - 1);
            const int iyc = min(max(iy, 0), Hd - 1);
            const float4 v4 = *(const float4*)&g_v[base + (iyc * Wd + ixc) * CC];

            acc.x = fmaf(w, v4.x, acc.x);
            acc.y = fmaf(w, v4.y, acc.y);
            acc.z = fmaf(w, v4.z, acc.z);
            acc.w = fmaf(w, v4.w, acc.w);
        }
    }

    // Reduce the 4 corner groups (lanes differing in bits 3,4)
#pragma unroll
    for (int ofs = 8; ofs <= 16; ofs <<= 1) {
        acc.x += __shfl_xor_sync(0xffffffffu, acc.x, ofs);
        acc.y += __shfl_xor_sync(0xffffffffu, acc.y, ofs);
        acc.z += __shfl_xor_sync(0xffffffffu, acc.z, ofs);
        acc.w += __shfl_xor_sync(0xffffffffu, acc.w, ofs);
    }

    if (lane < 8) {
        *(float4*)&g_tmp[(bq * HEADS + h) * HD + ch4 * 4] = acc;
    }
}

// ---------------------------------------------------------------------------
extern "C" void kernel_launch(void* const* d_in, const int* in_sizes, int n_in,
                              void* d_out, int out_size)
{
    const float* query  = (const float*)d_in[0];
    const float* refpts = (const float*)d_in[1];
    const float* value  = (const float*)d_in[2];
    const float* Wv     = (const float*)d_in[3];
    const float* bv     = (const float*)d_in[4];
    const float* Woff   = (const float*)d_in[5];
    const float* boff   = (const float*)d_in[6];
    const float* Wa     = (const float*)d_in[7];
    const float* ba     = (const float*)d_in[8];
    const float* Wo     = (const float*)d_in[9];
    const float* bo     = (const float*)d_in[10];
    float* out = (float*)d_out;

    float *p_v, *p_off, *p_a, *p_tmp;
    cudaGetSymbolAddress((void**)&p_v,   g_v);
    cudaGetSymbolAddress((void**)&p_off, g_off);
    cudaGetSymbolAddress((void**)&p_a,   g_a);
    cudaGetSymbolAddress((void**)&p_tmp, g_tmp);

    const int M = BB * NQ;              // 10752 = 84 * 128
    const int gy = M / GBm;             // 84

    // v = value @ Wv^T + bv
    gemm_tf32_kernel<<<dim3(CC / GBn, gy), 256>>>(value, Wv, bv, p_v, M, CC, CC);
    // off = query @ Woff^T + boff
    gemm_tf32_kernel<<<dim3(TP2 / GBn, gy), 256>>>(query, Woff, boff, p_off, M, TP2, CC);
    // a = query @ Wa^T + ba
    gemm_tf32_kernel<<<dim3((TP + GBn - 1) / GBn, gy), 256>>>(query, Wa, ba, p_a, M, TP, CC);
    // bilinear sampling (softmax fused, corner-parallel)
    sample_kernel<<<(BB * NQ * HEADS) / 8, 256>>>(refpts);
    // out = tmp @ Wo^T + bo
    gemm_tf32_kernel<<<dim3(CC / GBn, gy), 256>>>(p_tmp, Wo, bo, out, M, CC, CC);
}

// round 9
// speedup vs baseline: 3.3267x; 1.0865x over previous
#include <cuda_runtime.h>
#include <math.h>

// Problem constants
#define BB     2
#define HEADS  8
#define LEVELS 3
#define POINTS 4
#define CC     256
#define HD     32          // CC / HEADS
#define NV     5376        // 64*64 + 32*32 + 16*16
#define NQ     5376
#define TP     96          // HEADS*LEVELS*POINTS
#define TP2    192

// Padded value-tensor geometry: each level padded by a 1-cell zero ring.
// L0: 66x66 = 4356, L1: 34x34 = 1156, L2: 18x18 = 324.  Total 5836 cells/batch.
#define PNV    5836
#define P0     0
#define P1     4356
#define P2     5512
#define VP_TOTAL  (BB * PNV * CC)      // 2,988,032 floats

// Scratch (static device allocations — allowed by harness rules)
__device__ float g_vp[VP_TOTAL];           // padded value @ Wv^T + bv, (b, padded_cell, h, hd)
__device__ float g_off[BB * NQ * TP2];     // sampling offsets
__device__ float g_a[BB * NQ * TP];        // attention logits (softmax fused in sampler)
__device__ float g_tmp[BB * NQ * CC];      // sampled output, layout (b, q, h, hd)

// ---------------------------------------------------------------------------
// Zero the padded value buffer (border cells must be 0 every call; interior
// is overwritten by the v-GEMM). Full-buffer float4 memset, ~3us.
// ---------------------------------------------------------------------------
__global__ void __launch_bounds__(256) zero_vp_kernel()
{
    int i = blockIdx.x * blockDim.x + threadIdx.x;
    if (i < VP_TOTAL / 4)
        ((float4*)g_vp)[i] = make_float4(0.f, 0.f, 0.f, 0.f);
}

// ---------------------------------------------------------------------------
// Tensor-core GEMM (tf32 mma.sync): C[m,n] = sum_k A[m,k]*W[n,k] + bias[n]
// Block tile 128m x 64n, k-tile 32. 256 threads = 8 warps, each warp 32m x 32n
// (2 m16 x 4 n8 of m16n8k8). fp32 accum; inputs rounded to tf32.
// Register-prefetch double buffering: next k-tile's LDGs issue right after the
// post-store sync and retire under the 64-mma compute.
// pad_v != 0: epilogue remaps output rows into the padded g_vp layout.
// ---------------------------------------------------------------------------
#define GBm 128
#define GBn 64
#define GBk 32
#define SSTR 36   // smem row stride in words (32 + 4 pad -> conflict-free)

__device__ __forceinline__ unsigned f2tf32(float f) {
    unsigned u;
    asm("cvt.rna.tf32.f32 %0, %1;" : "=r"(u) : "f"(f));
    return u;
}

__device__ __forceinline__ int padded_row(int gm) {
    int b = gm / NV;
    int n = gm - b * NV;
    int pbase, cell;
    if (n < 4096)      { int y = n >> 6, x = n & 63;                pbase = P0; cell = (y + 1) * 66 + (x + 1); }
    else if (n < 5120) { int t = n - 4096; int y = t >> 5, x = t & 31; pbase = P1; cell = (y + 1) * 34 + (x + 1); }
    else               { int t = n - 5120; int y = t >> 4, x = t & 15; pbase = P2; cell = (y + 1) * 18 + (x + 1); }
    return b * PNV + pbase + cell;
}

__global__ void __launch_bounds__(256) gemm_tf32_kernel(
    const float* __restrict__ A, const float* __restrict__ W,
    const float* __restrict__ bias, float* __restrict__ C,
    int M, int N, int K, int pad_v)
{
    __shared__ unsigned As[GBm][SSTR];   // A tile, [m][k], tf32 bits
    __shared__ unsigned Ws[GBn][SSTR];   // W tile, [n][k], tf32 bits

    const int tid  = threadIdx.x;
    const int lane = tid & 31;
    const int warp = tid >> 5;
    const int wm   = warp >> 1;          // 0..3 -> m offset wm*32
    const int wn   = warp & 1;           // 0..1 -> n offset wn*32
    const int m0   = blockIdx.y * GBm;
    const int n0   = blockIdx.x * GBn;

    const int grp = lane >> 2;           // groupID (0..7)
    const int tig = lane & 3;            // threadID in group (0..3)

    // Per-thread fixed load coordinates (A: 4 float4s, W: 2 float4s per tile)
    int ar[4], ac[4];                    // A row in tile / k-float4 index
    size_t aoff[4];
#pragma unroll
    for (int j = 0; j < 4; j++) {
        int idx = tid + j * 256;
        ar[j] = idx >> 3;
        ac[j] = idx & 7;
        aoff[j] = (size_t)(m0 + ar[j]) * K + ac[j] * 4;
    }
    int wr[2], wc[2], wg[2];
    size_t woff[2];
#pragma unroll
    for (int j = 0; j < 2; j++) {
        int idx = tid + j * 256;
        wr[j] = idx >> 3;
        wc[j] = idx & 7;
        wg[j] = n0 + wr[j];
        woff[j] = (size_t)wg[j] * K + wc[j] * 4;
    }

    float c[2][4][4];
#pragma unroll
    for (int mt = 0; mt < 2; mt++)
#pragma unroll
        for (int nt = 0; nt < 4; nt++)
#pragma unroll
            for (int i = 0; i < 4; i++) c[mt][nt][i] = 0.f;

    // Prologue: fetch k0 = 0 tile into registers
    float4 pa[4], pw[2];
#pragma unroll
    for (int j = 0; j < 4; j++) pa[j] = *(const float4*)&A[aoff[j]];
#pragma unroll
    for (int j = 0; j < 2; j++)
        pw[j] = (wg[j] < N) ? *(const float4*)&W[woff[j]]
                            : make_float4(0.f, 0.f, 0.f, 0.f);

    for (int k0 = 0; k0 < K; k0 += GBk) {
        // Store prefetched tile (with tf32 rounding) to smem
#pragma unroll
        for (int j = 0; j < 4; j++) {
            uint4 u;
            u.x = f2tf32(pa[j].x); u.y = f2tf32(pa[j].y);
            u.z = f2tf32(pa[j].z); u.w = f2tf32(pa[j].w);
            *(uint4*)&As[ar[j]][ac[j] * 4] = u;
        }
#pragma unroll
        for (int j = 0; j < 2; j++) {
            uint4 u;
            u.x = f2tf32(pw[j].x); u.y = f2tf32(pw[j].y);
            u.z = f2tf32(pw[j].z); u.w = f2tf32(pw[j].w);
            *(uint4*)&Ws[wr[j]][wc[j] * 4] = u;
        }
        __syncthreads();

        // Prefetch next k-tile (LDGs retire under the mma compute below)
        const int kn = k0 + GBk;
        if (kn < K) {
#pragma unroll
            for (int j = 0; j < 4; j++) pa[j] = *(const float4*)&A[aoff[j] + kn];
#pragma unroll
            for (int j = 0; j < 2; j++)
                pw[j] = (wg[j] < N) ? *(const float4*)&W[woff[j] + kn]
                                    : make_float4(0.f, 0.f, 0.f, 0.f);
        }

#pragma unroll
        for (int kk = 0; kk < GBk; kk += 8) {
            unsigned a[2][4];
#pragma unroll
            for (int mt = 0; mt < 2; mt++) {
                int rb = wm * 32 + mt * 16;
                a[mt][0] = As[rb + grp][kk + tig];
                a[mt][1] = As[rb + grp + 8][kk + tig];
                a[mt][2] = As[rb + grp][kk + tig + 4];
                a[mt][3] = As[rb + grp + 8][kk + tig + 4];
            }
            unsigned b[4][2];
#pragma unroll
            for (int nt = 0; nt < 4; nt++) {
                int cb = wn * 32 + nt * 8;
                b[nt][0] = Ws[cb + grp][kk + tig];
                b[nt][1] = Ws[cb + grp][kk + tig + 4];
            }
#pragma unroll
            for (int mt = 0; mt < 2; mt++)
#pragma unroll
                for (int nt = 0; nt < 4; nt++) {
                    asm volatile(
                        "mma.sync.aligned.m16n8k8.row.col.f32.tf32.tf32.f32 "
                        "{%0,%1,%2,%3}, {%4,%5,%6,%7}, {%8,%9}, {%0,%1,%2,%3};"
                        : "+f"(c[mt][nt][0]), "+f"(c[mt][nt][1]),
                          "+f"(c[mt][nt][2]), "+f"(c[mt][nt][3])
                        : "r"(a[mt][0]), "r"(a[mt][1]), "r"(a[mt][2]), "r"(a[mt][3]),
                          "r"(b[nt][0]), "r"(b[nt][1]));
                }
        }
        __syncthreads();
    }

    // ---- epilogue ----
    int row0[2], row1[2];
#pragma unroll
    for (int mt = 0; mt < 2; mt++) {
        int gm = m0 + wm * 32 + mt * 16 + grp;
        row0[mt] = pad_v ? padded_row(gm) : gm;
        row1[mt] = pad_v ? padded_row(gm + 8) : gm + 8;
    }
#pragma unroll
    for (int nt = 0; nt < 4; nt++) {
        int gn = n0 + wn * 32 + nt * 8 + tig * 2;
        if (gn >= N) continue;
        float b0 = bias[gn];
        float b1 = bias[gn + 1];
#pragma unroll
        for (int mt = 0; mt < 2; mt++) {
            float2 o0 = make_float2(c[mt][nt][0] + b0, c[mt][nt][1] + b1);
            float2 o1 = make_float2(c[mt][nt][2] + b0, c[mt][nt][3] + b1);
            *(float2*)&C[(size_t)row0[mt] * N + gn] = o0;
            *(float2*)&C[(size_t)row1[mt] * N + gn] = o1;
        }
    }
}

// ---------------------------------------------------------------------------
// Bilinear sampling, corner-parallel float4 form, zero-padded value tensor:
// no clamps, no validity predicates — out-of-range corners read exact zeros.
// One warp per (b, q, head); lane = cg*8 + ch4.
// ---------------------------------------------------------------------------
__global__ void __launch_bounds__(256) sample_kernel(
    const float* __restrict__ refpts)
{
    const int warp = (blockIdx.x * blockDim.x + threadIdx.x) >> 5;
    const int lane = threadIdx.x & 31;
    const int total = BB * NQ * HEADS;
    if (warp >= total) return;

    const int h  = warp % HEADS;
    const int bq = warp / HEADS;      // b*NQ + q
    const int b  = bq / NQ;

    const int cg  = lane >> 3;        // corner 0..3
    const int dx  = cg & 1;
    const int dy  = cg >> 1;
    const int ch4 = lane & 7;         // float4 chunk within head

    const float rx = refpts[bq * 2 + 0];
    const float ry = refpts[bq * 2 + 1];

    const float* __restrict__ off   = g_off + bq * TP2 + h * (LEVELS * POINTS * 2);
    const float* __restrict__ logit = g_a   + bq * TP  + h * (LEVELS * POINTS);

    // Fused softmax over the 12 attention logits.
    float e[LEVELS * POINTS];
    float mx = -INFINITY;
#pragma unroll
    for (int i = 0; i < LEVELS * POINTS; i++) {
        e[i] = logit[i];
        mx = fmaxf(mx, e[i]);
    }
    float s = 0.f;
#pragma unroll
    for (int i = 0; i < LEVELS * POINTS; i++) { e[i] = __expf(e[i] - mx); s += e[i]; }
    const float inv = 1.f / s;

    const int plvl_start[LEVELS] = {P0, P1, P2};
    const int lvl_dim[LEVELS]    = {64, 32, 16};

    float4 acc = make_float4(0.f, 0.f, 0.f, 0.f);

#pragma unroll
    for (int lvl = 0; lvl < LEVELS; lvl++) {
        const int Wd = lvl_dim[lvl];
        const int Pw = Wd + 2;        // padded width
        // base index (floats) of padded (0,0) cell for this level/head/chunk
        const int base = (b * PNV + plvl_start[lvl]) * CC + h * HD + ch4 * 4;
        const float fW = (float)Wd;
#pragma unroll
        for (int p = 0; p < POINTS; p++) {
            float lx = rx + off[(lvl * POINTS + p) * 2 + 0];
            float ly = ry + off[(lvl * POINTS + p) * 2 + 1];
            lx = fminf(fmaxf(lx, 0.f), 1.f);
            ly = fminf(fmaxf(ly, 0.f), 1.f);
            const float aw = e[lvl * POINTS + p] * inv;

            const float x = lx * fW - 0.5f;
            const float y = ly * fW - 0.5f;   // Hd == Wd for all levels
            const float x0f = floorf(x);
            const float y0f = floorf(y);
            const int x0 = (int)x0f;
            const int y0 = (int)y0f;
            const float wx1 = x - x0f;
            const float wy1 = y - y0f;

            const float w = aw * (dx ? wx1 : 1.f - wx1) * (dy ? wy1 : 1.f - wy1);

            // padded cell: (y0+dy+1, x0+dx+1) — always in range
            const int cell = (y0 + dy + 1) * Pw + (x0 + dx + 1);
            const float4 v4 = *(const float4*)&g_vp[base + cell * CC];

            acc.x = fmaf(w, v4.x, acc.x);
            acc.y = fmaf(w, v4.y, acc.y);
            acc.z = fmaf(w, v4.z, acc.z);
            acc.w = fmaf(w, v4.w, acc.w);
        }
    }

    // Reduce the 4 corner groups (lanes differing in bits 3,4)
#pragma unroll
    for (int ofs = 8; ofs <= 16; ofs <<= 1) {
        acc.x += __shfl_xor_sync(0xffffffffu, acc.x, ofs);
        acc.y += __shfl_xor_sync(0xffffffffu, acc.y, ofs);
        acc.z += __shfl_xor_sync(0xffffffffu, acc.z, ofs);
        acc.w += __shfl_xor_sync(0xffffffffu, acc.w, ofs);
    }

    if (lane < 8) {
        *(float4*)&g_tmp[(bq * HEADS + h) * HD + ch4 * 4] = acc;
    }
}

// ---------------------------------------------------------------------------
extern "C" void kernel_launch(void* const* d_in, const int* in_sizes, int n_in,
                              void* d_out, int out_size)
{
    const float* query  = (const float*)d_in[0];
    const float* refpts = (const float*)d_in[1];
    const float* value  = (const float*)d_in[2];
    const float* Wv     = (const float*)d_in[3];
    const float* bv     = (const float*)d_in[4];
    const float* Woff   = (const float*)d_in[5];
    const float* boff   = (const float*)d_in[6];
    const float* Wa     = (const float*)d_in[7];
    const float* ba     = (const float*)d_in[8];
    const float* Wo     = (const float*)d_in[9];
    const float* bo     = (const float*)d_in[10];
    float* out = (float*)d_out;

    float *p_vp, *p_off, *p_a, *p_tmp;
    cudaGetSymbolAddress((void**)&p_vp,  g_vp);
    cudaGetSymbolAddress((void**)&p_off, g_off);
    cudaGetSymbolAddress((void**)&p_a,   g_a);
    cudaGetSymbolAddress((void**)&p_tmp, g_tmp);

    const int M = BB * NQ;              // 10752 = 84 * 128
    const int gy = M / GBm;             // 84

    // zero padded value buffer (border must be 0; interior overwritten below)
    zero_vp_kernel<<<(VP_TOTAL / 4 + 255) / 256, 256>>>();
    // v = value @ Wv^T + bv  -> padded layout
    gemm_tf32_kernel<<<dim3(CC / GBn, gy), 256>>>(value, Wv, bv, p_vp, M, CC, CC, 1);
    // off = query @ Woff^T + boff
    gemm_tf32_kernel<<<dim3(TP2 / GBn, gy), 256>>>(query, Woff, boff, p_off, M, TP2, CC, 0);
    // a = query @ Wa^T + ba
    gemm_tf32_kernel<<<dim3((TP + GBn - 1) / GBn, gy), 256>>>(query, Wa, ba, p_a, M, TP, CC, 0);
    // bilinear sampling (softmax fused, corner-parallel, padded v)
    sample_kernel<<<(BB * NQ * HEADS) / 8, 256>>>(refpts);
    // out = tmp @ Wo^T + bo
    gemm_tf32_kernel<<<dim3(CC / GBn, gy), 256>>>(p_tmp, Wo, bo, out, M, CC, CC, 0);
}